// round 8
// baseline (speedup 1.0000x reference)
#include <cuda_runtime.h>
#include <math.h>
#include <stdint.h>

// hidden_states: [16, 13, 512, 768] fp32, reduce over axis=2 (512)
// out: [16, 13, 2304] = concat(sum, std(ddof=1), max).
//
// R8: single-pass. One CTA per bl column (208 CTAs), full 512-row
// reduction with a 3-stage x 12KB cp.async.bulk pipeline; stats stay in
// registers; final output written directly. No scratch / atomics / fences.
// DRAM saturation comes from outstanding TMA bytes (208 x 36KB = 7.5MB),
// not CTA count.

#define BL     208
#define SEQ    512
#define HID    768
#define SROWS  4               // rows per stage
#define NST    3               // pipeline stages
#define NITER  (SEQ / SROWS)   // 128
#define TPB    256
#define STAGE_BYTES (SROWS * HID * 4)   // 12288

__device__ __forceinline__ uint32_t smem_u32(const void* p) {
    uint32_t a;
    asm("{ .reg .u64 t; cvta.to.shared.u64 t, %1; cvt.u32.u64 %0, t; }"
        : "=r"(a) : "l"(p));
    return a;
}
__device__ __forceinline__ void mbar_init(uint32_t bar, uint32_t cnt) {
    asm volatile("mbarrier.init.shared.b64 [%0], %1;" :: "r"(bar), "r"(cnt) : "memory");
}
__device__ __forceinline__ void mbar_arrive(uint32_t bar) {
    asm volatile("mbarrier.arrive.shared.b64 _, [%0];" :: "r"(bar) : "memory");
}
__device__ __forceinline__ void mbar_expect_tx(uint32_t bar, uint32_t tx) {
    asm volatile("mbarrier.arrive.expect_tx.shared.b64 _, [%0], %1;"
                 :: "r"(bar), "r"(tx) : "memory");
}
__device__ __forceinline__ void mbar_wait(uint32_t bar, uint32_t parity) {
    asm volatile(
        "{\n\t"
        ".reg .pred P;\n\t"
        "LAB_WAIT_%=:\n\t"
        "mbarrier.try_wait.parity.acquire.cta.shared::cta.b64 P, [%0], %1, 0x989680;\n\t"
        "@P bra.uni LAB_DONE_%=;\n\t"
        "bra.uni LAB_WAIT_%=;\n\t"
        "LAB_DONE_%=:\n\t"
        "}"
        :: "r"(bar), "r"(parity) : "memory");
}
__device__ __forceinline__ void bulk_ld(uint32_t dst_smem, const void* src,
                                        uint32_t bytes, uint32_t bar) {
    asm volatile(
        "cp.async.bulk.shared::cta.global.mbarrier::complete_tx::bytes "
        "[%0], [%1], %2, [%3];"
        :: "r"(dst_smem), "l"(src), "r"(bytes), "r"(bar) : "memory");
}

__global__ void __launch_bounds__(TPB) meanstdmax_kernel(
    const float* __restrict__ in, float* __restrict__ out)
{
    __shared__ __align__(128) float buf[NST][SROWS * HID];   // 36 KB
    __shared__ __align__(8) uint64_t full_bar[NST];
    __shared__ __align__(8) uint64_t empty_bar[NST];

    const int tid = threadIdx.x;
    const int bl  = blockIdx.x;

    const float* base = in + (size_t)bl * SEQ * HID;

    uint32_t full_a  = smem_u32(&full_bar[0]);
    uint32_t empty_a = smem_u32(&empty_bar[0]);
    uint32_t buf_a[NST];
    #pragma unroll
    for (int s = 0; s < NST; s++) buf_a[s] = smem_u32(&buf[s][0]);

    if (tid == 0) {
        #pragma unroll
        for (int s = 0; s < NST; s++) {
            mbar_init(full_a  + s * 8, 1);
            mbar_init(empty_a + s * 8, TPB);
        }
    }
    __syncthreads();

    if (tid == 0) {
        #pragma unroll
        for (int s = 0; s < NST; s++) {
            mbar_expect_tx(full_a + s * 8, STAGE_BYTES);
            bulk_ld(buf_a[s], base + (size_t)s * SROWS * HID, STAGE_BYTES,
                    full_a + s * 8);
        }
    }

    // per-thread columns: h = tid, tid+256, tid+512
    float s0 = 0.f, s1 = 0.f, s2 = 0.f;
    float q0 = 0.f, q1 = 0.f, q2 = 0.f;
    float m0 = -INFINITY, m1 = -INFINITY, m2 = -INFINITY;

    for (int it = 0; it < NITER; it++) {
        const int st = it % NST;
        const uint32_t par = (uint32_t)(it / NST) & 1u;

        mbar_wait(full_a + st * 8, par);

        const float* b = &buf[st][0];
        #pragma unroll
        for (int r = 0; r < SROWS; r++) {
            float v0 = b[r * HID + tid];
            float v1 = b[r * HID + tid + 256];
            float v2 = b[r * HID + tid + 512];
            s0 += v0; q0 += v0 * v0; m0 = fmaxf(m0, v0);
            s1 += v1; q1 += v1 * v1; m1 = fmaxf(m1, v1);
            s2 += v2; q2 += v2 * v2; m2 = fmaxf(m2, v2);
        }

        mbar_arrive(empty_a + st * 8);

        if (tid == 0 && it + NST < NITER) {
            mbar_wait(empty_a + st * 8, par);
            mbar_expect_tx(full_a + st * 8, STAGE_BYTES);
            bulk_ld(buf_a[st], base + (size_t)(it + NST) * SROWS * HID,
                    STAGE_BYTES, full_a + st * 8);
        }
    }

    // finalize + direct output
    const float inv_n  = 1.0f / SEQ;
    const float inv_n1 = 1.0f / (SEQ - 1);

    float sd0 = sqrtf(fmaxf((q0 - s0 * (s0 * inv_n)) * inv_n1, 0.0f));
    float sd1 = sqrtf(fmaxf((q1 - s1 * (s1 * inv_n)) * inv_n1, 0.0f));
    float sd2 = sqrtf(fmaxf((q2 - s2 * (s2 * inv_n)) * inv_n1, 0.0f));

    float* o = out + (size_t)bl * (3 * HID);
    o[tid]              = s0;  o[tid + 256]           = s1;  o[tid + 512]           = s2;
    o[HID + tid]        = sd0; o[HID + tid + 256]     = sd1; o[HID + tid + 512]     = sd2;
    o[2 * HID + tid]    = m0;  o[2 * HID + tid + 256] = m1;  o[2 * HID + tid + 512] = m2;
}

extern "C" void kernel_launch(void* const* d_in, const int* in_sizes, int n_in,
                              void* d_out, int out_size)
{
    const float* in = (const float*)d_in[0];
    float* out = (float*)d_out;

    meanstdmax_kernel<<<BL, TPB>>>(in, out);   // 208 CTAs, 1-2 per SM
}

// round 9
// speedup vs baseline: 1.1185x; 1.1185x over previous
#include <cuda_runtime.h>
#include <math.h>
#include <stdint.h>

// hidden_states: [16, 13, 512, 768] fp32, reduce over axis=2 (512)
// out: [16, 13, 2304] = concat(sum, std(ddof=1), max).
//
// R9: 2-CTA cluster + DSMEM merge, single kernel.
// Each bl -> cluster of 2 CTAs (256 rows each), 416 CTAs total
// (148 = 2*74, cluster=2 packs perfectly; ~3 CTAs/SM keeps TMA queues deep).
// 3-stage x 12KB cp.async.bulk pipeline per CTA. Rank1 sends its 9KB of
// partials to rank0's smem via mapa + st.shared::cluster; one cluster
// barrier; rank0 merges in-register and writes the output directly.
// No scratch, no atomics, no second kernel.

#define BL     208
#define SEQ    512
#define HID    768
#define RPC    256             // rows per CTA
#define SROWS  4               // rows per stage
#define NST    3               // pipeline stages
#define NITER  (RPC / SROWS)   // 64
#define TPB    256
#define STAGE_BYTES (SROWS * HID * 4)   // 12288

__device__ __forceinline__ uint32_t smem_u32(const void* p) {
    uint32_t a;
    asm("{ .reg .u64 t; cvta.to.shared.u64 t, %1; cvt.u32.u64 %0, t; }"
        : "=r"(a) : "l"(p));
    return a;
}
__device__ __forceinline__ void mbar_init(uint32_t bar, uint32_t cnt) {
    asm volatile("mbarrier.init.shared.b64 [%0], %1;" :: "r"(bar), "r"(cnt) : "memory");
}
__device__ __forceinline__ void mbar_arrive(uint32_t bar) {
    asm volatile("mbarrier.arrive.shared.b64 _, [%0];" :: "r"(bar) : "memory");
}
__device__ __forceinline__ void mbar_expect_tx(uint32_t bar, uint32_t tx) {
    asm volatile("mbarrier.arrive.expect_tx.shared.b64 _, [%0], %1;"
                 :: "r"(bar), "r"(tx) : "memory");
}
__device__ __forceinline__ void mbar_wait(uint32_t bar, uint32_t parity) {
    asm volatile(
        "{\n\t"
        ".reg .pred P;\n\t"
        "LAB_WAIT_%=:\n\t"
        "mbarrier.try_wait.parity.acquire.cta.shared::cta.b64 P, [%0], %1, 0x989680;\n\t"
        "@P bra.uni LAB_DONE_%=;\n\t"
        "bra.uni LAB_WAIT_%=;\n\t"
        "LAB_DONE_%=:\n\t"
        "}"
        :: "r"(bar), "r"(parity) : "memory");
}
__device__ __forceinline__ void bulk_ld(uint32_t dst_smem, const void* src,
                                        uint32_t bytes, uint32_t bar) {
    asm volatile(
        "cp.async.bulk.shared::cta.global.mbarrier::complete_tx::bytes "
        "[%0], [%1], %2, [%3];"
        :: "r"(dst_smem), "l"(src), "r"(bytes), "r"(bar) : "memory");
}
__device__ __forceinline__ uint32_t mapa_rank(uint32_t addr, uint32_t rank) {
    uint32_t r;
    asm("mapa.shared::cluster.u32 %0, %1, %2;" : "=r"(r) : "r"(addr), "r"(rank));
    return r;
}
__device__ __forceinline__ void st_cluster_f32(uint32_t addr, float v) {
    asm volatile("st.shared::cluster.f32 [%0], %1;" :: "r"(addr), "f"(v) : "memory");
}

__global__ void __launch_bounds__(TPB) __cluster_dims__(2, 1, 1)
meanstdmax_kernel(const float* __restrict__ in, float* __restrict__ out)
{
    __shared__ __align__(128) float buf[NST][SROWS * HID];   // 36 KB
    __shared__ __align__(16)  float part[3 * HID];           // 9 KB (rank0 recv)
    __shared__ __align__(8)   uint64_t full_bar[NST];
    __shared__ __align__(8)   uint64_t empty_bar[NST];

    const int tid = threadIdx.x;

    uint32_t rank;
    asm("mov.u32 %0, %%cluster_ctarank;" : "=r"(rank));

    const int bl = blockIdx.x >> 1;     // cluster id
    const float* base = in + (size_t)bl * SEQ * HID + (size_t)rank * RPC * HID;

    uint32_t full_a  = smem_u32(&full_bar[0]);
    uint32_t empty_a = smem_u32(&empty_bar[0]);
    uint32_t part_a  = smem_u32(&part[0]);
    uint32_t buf_a[NST];
    #pragma unroll
    for (int s = 0; s < NST; s++) buf_a[s] = smem_u32(&buf[s][0]);

    if (tid == 0) {
        #pragma unroll
        for (int s = 0; s < NST; s++) {
            mbar_init(full_a  + s * 8, 1);
            mbar_init(empty_a + s * 8, TPB);
        }
    }
    __syncthreads();

    if (tid == 0) {
        #pragma unroll
        for (int s = 0; s < NST; s++) {
            mbar_expect_tx(full_a + s * 8, STAGE_BYTES);
            bulk_ld(buf_a[s], base + (size_t)s * SROWS * HID, STAGE_BYTES,
                    full_a + s * 8);
        }
    }

    // per-thread columns: h = tid, tid+256, tid+512
    float s0 = 0.f, s1 = 0.f, s2 = 0.f;
    float q0 = 0.f, q1 = 0.f, q2 = 0.f;
    float m0 = -INFINITY, m1 = -INFINITY, m2 = -INFINITY;

    for (int it = 0; it < NITER; it++) {
        const int st = it % NST;
        const uint32_t par = (uint32_t)(it / NST) & 1u;

        mbar_wait(full_a + st * 8, par);

        const float* b = &buf[st][0];
        #pragma unroll
        for (int r = 0; r < SROWS; r++) {
            float v0 = b[r * HID + tid];
            float v1 = b[r * HID + tid + 256];
            float v2 = b[r * HID + tid + 512];
            s0 += v0; q0 += v0 * v0; m0 = fmaxf(m0, v0);
            s1 += v1; q1 += v1 * v1; m1 = fmaxf(m1, v1);
            s2 += v2; q2 += v2 * v2; m2 = fmaxf(m2, v2);
        }

        mbar_arrive(empty_a + st * 8);

        if (tid == 0 && it + NST < NITER) {
            mbar_wait(empty_a + st * 8, par);
            mbar_expect_tx(full_a + st * 8, STAGE_BYTES);
            bulk_ld(buf_a[st], base + (size_t)(it + NST) * SROWS * HID,
                    STAGE_BYTES, full_a + st * 8);
        }
    }

    // rank1 -> rank0 DSMEM transfer of partials: layout part[stat*HID + h]
    if (rank == 1) {
        uint32_t r0 = mapa_rank(part_a, 0);
        st_cluster_f32(r0 + 4 * (tid),                 s0);
        st_cluster_f32(r0 + 4 * (tid + 256),           s1);
        st_cluster_f32(r0 + 4 * (tid + 512),           s2);
        st_cluster_f32(r0 + 4 * (HID + tid),           q0);
        st_cluster_f32(r0 + 4 * (HID + tid + 256),     q1);
        st_cluster_f32(r0 + 4 * (HID + tid + 512),     q2);
        st_cluster_f32(r0 + 4 * (2 * HID + tid),       m0);
        st_cluster_f32(r0 + 4 * (2 * HID + tid + 256), m1);
        st_cluster_f32(r0 + 4 * (2 * HID + tid + 512), m2);
    }

    asm volatile("barrier.cluster.arrive.aligned;" ::: "memory");
    asm volatile("barrier.cluster.wait.aligned;"   ::: "memory");

    if (rank == 0) {
        s0 += part[tid];              s1 += part[tid + 256];              s2 += part[tid + 512];
        q0 += part[HID + tid];        q1 += part[HID + tid + 256];        q2 += part[HID + tid + 512];
        m0 = fmaxf(m0, part[2 * HID + tid]);
        m1 = fmaxf(m1, part[2 * HID + tid + 256]);
        m2 = fmaxf(m2, part[2 * HID + tid + 512]);

        const float inv_n  = 1.0f / SEQ;
        const float inv_n1 = 1.0f / (SEQ - 1);
        float sd0 = sqrtf(fmaxf((q0 - s0 * (s0 * inv_n)) * inv_n1, 0.0f));
        float sd1 = sqrtf(fmaxf((q1 - s1 * (s1 * inv_n)) * inv_n1, 0.0f));
        float sd2 = sqrtf(fmaxf((q2 - s2 * (s2 * inv_n)) * inv_n1, 0.0f));

        float* o = out + (size_t)bl * (3 * HID);
        o[tid]              = s0;  o[tid + 256]           = s1;  o[tid + 512]           = s2;
        o[HID + tid]        = sd0; o[HID + tid + 256]     = sd1; o[HID + tid + 512]     = sd2;
        o[2 * HID + tid]    = m0;  o[2 * HID + tid + 256] = m1;  o[2 * HID + tid + 512] = m2;
    }
}

extern "C" void kernel_launch(void* const* d_in, const int* in_sizes, int n_in,
                              void* d_out, int out_size)
{
    const float* in = (const float*)d_in[0];
    float* out = (float*)d_out;

    meanstdmax_kernel<<<BL * 2, TPB>>>(in, out);   // 416 CTAs, 208 clusters of 2
}